// round 14
// baseline (speedup 1.0000x reference)
#include <cuda_runtime.h>
#include <math.h>

#define B_        64
#define SEQ       784
#define SEQ_OUT   196
#define C_IN      512
#define KEY_DIM   32
#define NUM_HEADS 16
#define D_V       128
#define OUT_KV    2560
#define OUT_PROJ  2048
#define C_OUT     768
#define N_OFF     784
#define RES_OUT   14
#define SCALE_F   0.17677669529663687f
#define BN_EPS    1e-5f

// ---- scratch (static device globals; allocation-free) ----
__device__ float g_K   [(size_t)B_*NUM_HEADS*SEQ*KEY_DIM];   // d-permuted
__device__ float g_V   [(size_t)B_*NUM_HEADS*SEQ*D_V];
__device__ float g_Q   [(size_t)B_*NUM_HEADS*SEQ_OUT*KEY_DIM]; // d-permuted
__device__ float g_HS  [(size_t)B_*SEQ_OUT*OUT_PROJ];        // k-permuted
__device__ float g_Bias[(size_t)NUM_HEADS*SEQ_OUT*SEQ];
__device__ float g_Xr  [(size_t)B_*SEQ*C_IN];                // tf32, k-permuted
__device__ float g_Wkv [(size_t)OUT_KV*C_IN];                // tf32, k-permuted
__device__ float g_Wq  [(size_t)KEY_DIM*NUM_HEADS*C_IN];     // tf32, k-permuted
__device__ float g_Wp  [(size_t)C_OUT*OUT_PROJ];             // tf32, k-permuted

__device__ __forceinline__ unsigned f2tf32(float f) {
    unsigned r;
    asm("cvt.rna.tf32.f32 %0, %1;" : "=r"(r) : "f"(f));
    return r;
}
__device__ __forceinline__ float rtf32(float f) { return __uint_as_float(f2tf32(f)); }

__device__ __forceinline__ unsigned sm_u32(const void* p) {
    return (unsigned)__cvta_generic_to_shared(p);
}
#define CPA16(dst, src) asm volatile("cp.async.cg.shared.global [%0], [%1], 16;" :: "r"(dst), "l"(src))
#define CPCOMMIT()      asm volatile("cp.async.commit_group;")
#define CPWAIT(n)       asm volatile("cp.async.wait_group %0;" :: "n"(n))

__device__ __forceinline__ void mma_tf32(float* c, const unsigned* a, const unsigned* b) {
    asm volatile(
        "mma.sync.aligned.m16n8k8.row.col.f32.tf32.tf32.f32 "
        "{%0,%1,%2,%3}, {%4,%5,%6,%7}, {%8,%9}, {%0,%1,%2,%3};"
        : "+f"(c[0]), "+f"(c[1]), "+f"(c[2]), "+f"(c[3])
        : "r"(a[0]), "r"(a[1]), "r"(a[2]), "r"(a[3]), "r"(b[0]), "r"(b[1]));
}

// ============================================================
// Merged tf32 round + k-permutation for all four operands.
// slot(k) = 2*(k&3) + ((k&4)>>2) within each 8-block.
// ============================================================
#define N4_X  (B_*SEQ*C_IN/4)
#define N4_KV (OUT_KV*C_IN/4)
#define N4_Q  (KEY_DIM*NUM_HEADS*C_IN/4)
#define N4_P  (C_OUT*OUT_PROJ/4)
#define N4_ALL (N4_X + N4_KV + N4_Q + N4_P)

__global__ void round_perm_all(const float* __restrict__ x,
                               const float* __restrict__ kvw,
                               const float* __restrict__ qw,
                               const float* __restrict__ pw)
{
    int i = blockIdx.x * 256 + threadIdx.x;
    if (i >= N4_ALL) return;
    const float* src;
    float* dst;
    int j = i;
    if (j < N4_X)            { src = x;   dst = g_Xr;  }
    else if ((j -= N4_X) < N4_KV) { src = kvw; dst = g_Wkv; }
    else if ((j -= N4_KV) < N4_Q) { src = qw;  dst = g_Wq;  }
    else { j -= N4_Q;          src = pw;  dst = g_Wp;  }

    int o = j * 4, blk = o & ~7, s = o & 7;
    float4 v;
    float* pv = (float*)&v;
    #pragma unroll
    for (int e = 0; e < 4; e++) {
        int se = s + e;
        int k = (se & 1) ? 4 + (se >> 1) : (se >> 1);
        pv[e] = rtf32(src[blk + k]);
    }
    ((float4*)dst)[j] = v;
}

// ============================================================
// Bias pre-gather
// ============================================================
__global__ void bias_gather(const float* __restrict__ biases,
                            const int*   __restrict__ idxs)
{
    int i = blockIdx.x * 256 + threadIdx.x;
    if (i < SEQ_OUT * SEQ) {
        int idx = idxs[i];
        #pragma unroll
        for (int h = 0; h < NUM_HEADS; h++)
            g_Bias[(size_t)h * SEQ_OUT * SEQ + i] = biases[h * N_OFF + idx];
    }
}

// ============================================================
// TF32 GEMM (R10/R13): k-permuted operands, LDS.64 frag loads.
// ============================================================
#define GST  24
#define NSTG 4
#define GEMM_SMEM_BYTES (2*NSTG*128*GST*4)   // 98304

template<int MODE>
__global__ void __launch_bounds__(256, 2)
gemm_tc(const float* __restrict__ A, const float* __restrict__ W,
        const float* __restrict__ bng, const float* __restrict__ bnb,
        const float* __restrict__ bnm, const float* __restrict__ bnv,
        float* __restrict__ out, int M, int N, int K)
{
    extern __shared__ float smemf[];
    float* SA = smemf;
    float* SB = smemf + NSTG*128*GST;

    const int t    = threadIdx.x;
    const int warp = t >> 5, lane = t & 31;
    const int wm   = warp >> 2, wn = warp & 3;
    const int bm   = blockIdx.x * 128;
    const int bnn  = blockIdx.y * 128;
    const int lg   = lane >> 2, lc = lane & 3;

    const int r0 = t >> 2,        d0 = (t & 3) * 4;
    const int r1 = (t + 256) >> 2, d1 = ((t + 256) & 3) * 4;

    auto a_row = [&](int r) -> const float* {
        if (MODE == 1) {
            int row = bm + r;
            int b = row / SEQ_OUT, sq = row - b * SEQ_OUT;
            int rr = sq / RES_OUT, cc = sq - rr * RES_OUT;
            return A + ((size_t)b * SEQ + (2*rr*28 + 2*cc)) * C_IN;
        }
        if (MODE == 2) {
            return g_HS + (size_t)(bm + r) * K;
        }
        return A + (size_t)(bm + r) * K;
    };
    const float* aP0 = a_row(r0);
    const float* aP1 = a_row(r1);
    const float* bP0 = W + (size_t)(bnn + r0) * K;
    const float* bP1 = W + (size_t)(bnn + r1) * K;

    const unsigned sbase = sm_u32(smemf);
    const unsigned aA0 = sbase + (r0*GST + d0)*4;
    const unsigned aA1 = sbase + (r1*GST + d1)*4;
    const unsigned bA0 = sbase + (NSTG*128*GST + r0*GST + d0)*4;
    const unsigned bA1 = sbase + (NSTG*128*GST + r1*GST + d1)*4;

    auto issue = [&](int s, int k0) {
        unsigned so = s * 128*GST*4;
        CPA16(aA0 + so, aP0 + k0 + d0);
        CPA16(aA1 + so, aP1 + k0 + d1);
        CPA16(bA0 + so, bP0 + k0 + d0);
        CPA16(bA1 + so, bP1 + k0 + d1);
    };

    float acc[16][4];
    #pragma unroll
    for (int i = 0; i < 16; i++)
        #pragma unroll
        for (int j = 0; j < 4; j++) acc[i][j] = 0.f;

    const int nIter = K >> 4;
    #pragma unroll
    for (int s = 0; s < 3; s++) { issue(s, s << 4); CPCOMMIT(); }

    for (int it = 0; it < nIter; ++it) {
        CPWAIT(2);
        __syncthreads();
        const float* pA = SA + (it & 3) * 128*GST;
        const float* pB = SB + (it & 3) * 128*GST;

        #pragma unroll
        for (int g = 0; g < 2; g++) {
            const int ko = g*8 + 2*lc;
            unsigned af[4][4], bf[4][2];
            #pragma unroll
            for (int mt = 0; mt < 4; mt++) {
                int r = wm*64 + mt*16 + lg;
                uint2 p0 = *(const uint2*)&pA[r*GST + ko];
                uint2 p1 = *(const uint2*)&pA[(r+8)*GST + ko];
                af[mt][0] = p0.x;  af[mt][2] = p0.y;
                af[mt][1] = p1.x;  af[mt][3] = p1.y;
            }
            #pragma unroll
            for (int nt = 0; nt < 4; nt++) {
                int rn = wn*32 + nt*8 + lg;
                uint2 p = *(const uint2*)&pB[rn*GST + ko];
                bf[nt][0] = p.x;   bf[nt][1] = p.y;
            }
            #pragma unroll
            for (int mt = 0; mt < 4; mt++)
                #pragma unroll
                for (int nt = 0; nt < 4; nt++)
                    mma_tf32(acc[mt*4 + nt], af[mt], bf[nt]);
        }

        if (it + 3 < nIter) issue((it + 3) & 3, (it + 3) << 4);
        CPCOMMIT();
    }

    // ---- BN epilogue + scatter ----
    const int s0p = (lc < 2) ? 4*lc : 4*lc - 7;
    #pragma unroll
    for (int nt = 0; nt < 4; nt++) {
        int c0 = bnn + wn*32 + nt*8 + 2*lc;
        float sc0 = bng[c0]     * rsqrtf(bnv[c0]     + BN_EPS);
        float sh0 = bnb[c0]     - bnm[c0]     * sc0;
        float sc1 = bng[c0 + 1] * rsqrtf(bnv[c0 + 1] + BN_EPS);
        float sh1 = bnb[c0 + 1] - bnm[c0 + 1] * sc1;
        #pragma unroll
        for (int mt = 0; mt < 4; mt++) {
            #pragma unroll
            for (int half = 0; half < 2; half++) {
                int m = bm + wm*64 + mt*16 + lg + half*8;
                float y0 = acc[mt*4 + nt][half*2 + 0] * sc0 + sh0;
                float y1 = acc[mt*4 + nt][half*2 + 1] * sc1 + sh1;
                if (MODE == 0) {
                    int b = m / SEQ, s = m - b * SEQ;
                    int h = c0 / (KEY_DIM + D_V);
                    int c = c0 - h * (KEY_DIM + D_V);
                    if (c < KEY_DIM) {
                        float* base = &g_K[(((size_t)(b*NUM_HEADS+h))*SEQ + s)*KEY_DIM + (c & ~7)];
                        base[s0p]     = rtf32(y0);
                        base[s0p + 2] = rtf32(y1);
                    } else {
                        float* p = &g_V[(((size_t)(b*NUM_HEADS+h))*SEQ + s)*D_V + (c - KEY_DIM)];
                        p[0] = rtf32(y0); p[1] = rtf32(y1);
                    }
                } else if (MODE == 1) {
                    int b = m / SEQ_OUT, sq = m - b * SEQ_OUT;
                    int h = c0 / KEY_DIM, d = c0 - h * KEY_DIM;
                    float* base = &g_Q[(((size_t)(b*NUM_HEADS+h))*SEQ_OUT + sq)*KEY_DIM + (d & ~7)];
                    base[s0p]     = rtf32(y0);
                    base[s0p + 2] = rtf32(y1);
                } else {
                    float* p = &out[(size_t)m * C_OUT + c0];
                    p[0] = y0; p[1] = y1;
                }
            }
        }
    }
}

// ============================================================
// Flash-style tf32 attention (R13 + bias via __ldg registers):
// no sB staging — per-chunk bias prefetched into registers before
// the CPWAIT, hiding the L2 latency under the K-wait.
// ============================================================
#define QB  28
#define KC  112
#define NCH 7

#define QST 40
#define SST 120
#define W_SQ (32*QST)
#define W_SK (KC*QST)
#define W_SV 15232
#define W_SS (32*SST)
#define ATTN_WORDS (W_SQ + W_SK + W_SV + W_SS + 96)
#define ATTN_BYTES (ATTN_WORDS * 4)

__global__ void __launch_bounds__(256, 2)
attn_tc()
{
    extern __shared__ unsigned smw[];
    unsigned* sQ = smw;
    unsigned* sK = sQ + W_SQ;
    unsigned* sV = sK + W_SK;
    float*    sS = (float*)(sV + W_SV);
    float*    sM = sS + W_SS;
    float*    sL = sM + 32;
    float*    sF = sL + 32;

    const int t    = threadIdx.x;
    const int warp = t >> 5, lane = t & 31;
    const int cta  = blockIdx.x;
    const int qb   = cta % 7;
    const int h    = (cta / 7) % NUM_HEADS;
    const int b    = cta / (7 * NUM_HEADS);

    const float* Kp = g_K + ((size_t)(b*NUM_HEADS+h))*SEQ*KEY_DIM;
    const float* Vp = g_V + ((size_t)(b*NUM_HEADS+h))*SEQ*D_V;
    const float* Qp = g_Q + (((size_t)(b*NUM_HEADS+h))*SEQ_OUT + qb*QB)*KEY_DIM;
    const float* Bp = g_Bias + ((size_t)h*SEQ_OUT + qb*QB)*SEQ;

    const unsigned sKb = sm_u32(sK);
    const unsigned sVb = sm_u32(sV);

    auto stage_k = [&](int kc) {
        for (int i = t*4; i < KC*KEY_DIM; i += 1024) {
            int r = i >> 5, d = i & 31;
            CPA16(sKb + (r*QST + d)*4, &Kp[(size_t)kc*KEY_DIM + i]);
        }
        CPCOMMIT();
    };
    auto stage_v = [&](int kc) {
        for (int i = t*4; i < KC*D_V; i += 1024) {
            int r = i >> 7, d = i & 127;
            CPA16(sVb + (r*136 + d)*4, &Vp[(size_t)kc*D_V + i]);
        }
        CPCOMMIT();
    };

    for (int i = t; i < 32*32; i += 256) {
        int r = i >> 5, d = i & 31;
        float v = (r < QB) ? Qp[r*KEY_DIM + d] : 0.f;
        sQ[r*QST + d] = __float_as_uint(v);
    }
    if (t < 32) { sM[t] = -1e30f; sL[t] = 0.f; sF[t] = 1.f; }

    // prologue: chunk 0 staging
    stage_k(0);   // A0
    stage_v(0);   // B0

    float acc[2][2][4];
    #pragma unroll
    for (int mt = 0; mt < 2; mt++)
        #pragma unroll
        for (int nt = 0; nt < 2; nt++)
            #pragma unroll
            for (int e = 0; e < 4; e++) acc[mt][nt][e] = 0.f;

    const int lg = lane >> 2;
    const int lc = lane & 3;
    const int s0p = (lc < 2) ? 4*lc : 4*lc - 7;

    const int nt0 = (warp < 6) ? warp*2 : 6 + warp;
    const int ntc = (warp < 6) ? 2 : 1;

    for (int ch = 0; ch < NCH; ch++) {
        const int kc = ch * KC;

        // ---- prefetch this chunk's bias into regs (L2; hidden by wait) ----
        float2 breg[2][2];   // [nti][mt] = (b lo col, b hi col) per row pair
        float2 breg2[2][2];  // row r0+8
        #pragma unroll
        for (int nti = 0; nti < 2; nti++) {
            if (nti < ntc) {
                int col = (nt0 + nti)*8 + 2*lc;
                #pragma unroll
                for (int mt = 0; mt < 2; mt++) {
                    int r0 = mt*16 + lg;
                    breg[nti][mt]  = (r0   < QB) ? __ldg((const float2*)&Bp[(size_t)r0*SEQ + kc + col])
                                                 : make_float2(0.f, 0.f);
                    breg2[nti][mt] = (r0+8 < QB) ? __ldg((const float2*)&Bp[(size_t)(r0+8)*SEQ + kc + col])
                                                 : make_float2(0.f, 0.f);
                }
            }
        }

        // A_ch (K) done; B_ch (V) may still be in flight
        CPWAIT(1);
        __syncthreads();

        // ---- QK^T (uint2 fragment loads from permuted sQ/sK) ----
        for (int nti = 0; nti < ntc; nti++) {
            int ntile = nt0 + nti;
            float c[2][4] = {};
            #pragma unroll
            for (int ks = 0; ks < 4; ks++) {
                const int ko = ks*8 + 2*lc;
                uint2 kk2 = *(const uint2*)&sK[(ntile*8 + lg)*QST + ko];
                unsigned bb[2] = { kk2.x, kk2.y };
                #pragma unroll
                for (int mt = 0; mt < 2; mt++) {
                    int r0 = mt*16 + lg;
                    uint2 q0 = *(const uint2*)&sQ[r0*QST + ko];
                    uint2 q1 = *(const uint2*)&sQ[(r0+8)*QST + ko];
                    unsigned a[4] = { q0.x, q1.x, q0.y, q1.y };
                    mma_tf32(c[mt], a, bb);
                }
            }
            #pragma unroll
            for (int mt = 0; mt < 2; mt++) {
                int r0 = mt*16 + lg;
                int ps  = ntile*8 + s0p;
                sS[r0*SST + ps]           = c[mt][0]*SCALE_F + breg[nti][mt].x;
                sS[r0*SST + ps + 2]       = c[mt][1]*SCALE_F + breg[nti][mt].y;
                sS[(r0+8)*SST + ps]       = c[mt][2]*SCALE_F + breg2[nti][mt].x;
                sS[(r0+8)*SST + ps + 2]   = c[mt][3]*SCALE_F + breg2[nti][mt].y;
            }
        }
        __syncthreads();   // all warps done reading sK

        // prefetch next chunk's K into the dead buffer
        if (ch + 1 < NCH) stage_k((ch + 1) * KC);   // A_{ch+1}

        // ---- online softmax: warps 0-6 x 4 rows, interleaved chains ----
        if (warp < 7) {
            float4 v[4];
            float  mx[4], sum[4];
            #pragma unroll
            for (int i = 0; i < 4; i++) {
                int q = warp*4 + i;
                if (lane < 28) v[i] = *(const float4*)&sS[q*SST + lane*4];
                else v[i] = make_float4(-1e30f, -1e30f, -1e30f, -1e30f);
                mx[i] = fmaxf(fmaxf(v[i].x, v[i].y), fmaxf(v[i].z, v[i].w));
            }
            #pragma unroll
            for (int o = 16; o; o >>= 1) {
                #pragma unroll
                for (int i = 0; i < 4; i++)
                    mx[i] = fmaxf(mx[i], __shfl_xor_sync(~0u, mx[i], o));
            }
            float m_new[4], fac[4];
            #pragma unroll
            for (int i = 0; i < 4; i++) {
                int q = warp*4 + i;
                float m_old = sM[q];
                m_new[i] = fmaxf(m_old, mx[i]);
                fac[i]   = __expf(m_old - m_new[i]);
                float e0 = __expf(v[i].x - m_new[i]);
                float e1 = __expf(v[i].y - m_new[i]);
                float e2 = __expf(v[i].z - m_new[i]);
                float e3 = __expf(v[i].w - m_new[i]);
                v[i] = make_float4(e0, e1, e2, e3);
                sum[i] = (lane < 28) ? (e0 + e1 + e2 + e3) : 0.f;
            }
            #pragma unroll
            for (int o = 16; o; o >>= 1) {
                #pragma unroll
                for (int i = 0; i < 4; i++)
                    sum[i] += __shfl_xor_sync(~0u, sum[i], o);
            }
            #pragma unroll
            for (int i = 0; i < 4; i++) {
                int q = warp*4 + i;
                if (lane < 28)
                    *(float4*)&sS[q*SST + lane*4] = v[i];
                if (lane == 0) {
                    sM[q] = m_new[i];
                    sL[q] = sL[q]*fac[i] + sum[i];
                    sF[q] = fac[i];
                }
            }
        }

        // B_ch (V) done; A_{ch+1} may remain in flight
        if (ch + 1 < NCH) { CPWAIT(1); } else { CPWAIT(0); }
        __syncthreads();

        // ---- rescale accumulators ----
        {
            float f00 = sF[lg],      f01 = sF[lg + 8];
            float f10 = sF[lg + 16], f11 = sF[lg + 24];
            #pragma unroll
            for (int nt = 0; nt < 2; nt++) {
                acc[0][nt][0] *= f00; acc[0][nt][1] *= f00;
                acc[0][nt][2] *= f01; acc[0][nt][3] *= f01;
                acc[1][nt][0] *= f10; acc[1][nt][1] *= f10;
                acc[1][nt][2] *= f11; acc[1][nt][3] *= f11;
            }
        }

        // ---- PV accumulate ----
        #pragma unroll
        for (int ks = 0; ks < 14; ks++) {
            const int ko = ks*8 + 2*lc;
            unsigned a[2][4];
            #pragma unroll
            for (int mt = 0; mt < 2; mt++) {
                int r0 = mt*16 + lg;
                uint2 p0 = *(const uint2*)&sS[r0*SST + ko];
                uint2 p1 = *(const uint2*)&sS[(r0+8)*SST + ko];
                a[mt][0] = p0.x; a[mt][2] = p0.y;
                a[mt][1] = p1.x; a[mt][3] = p1.y;
            }
            #pragma unroll
            for (int nt = 0; nt < 2; nt++) {
                int n = warp*16 + nt*8 + lg;
                unsigned bb[2];
                bb[0] = sV[(ks*8 + lc)*136 + n];
                bb[1] = sV[(ks*8 + lc + 4)*136 + n];
                mma_tf32(acc[0][nt], a[0], bb);
                mma_tf32(acc[1][nt], a[1], bb);
            }
        }
        __syncthreads();   // all warps done reading sV (and sS)

        // prefetch next chunk's V into the dead sV buffer
        if (ch + 1 < NCH) stage_v((ch + 1) * KC);   // B_{ch+1}
    }

    // ---- epilogue: /l, hardswish, tf32-round, k-permuted HS store ----
    #pragma unroll
    for (int mt = 0; mt < 2; mt++) {
        int rA = mt*16 + lg, rB = rA + 8;
        float invA = 1.f / sL[rA];
        float invB = 1.f / sL[rB];
        #pragma unroll
        for (int nt = 0; nt < 2; nt++) {
            int blk = h*D_V + warp*16 + nt*8;
            #pragma unroll
            for (int half = 0; half < 2; half++) {
                int r = half ? rB : rA;
                if (r >= QB) continue;
                float inv = half ? invB : invA;
                float x0 = acc[mt][nt][half*2 + 0]*inv;
                float x1 = acc[mt][nt][half*2 + 1]*inv;
                float h0 = rtf32(x0 * fminf(fmaxf(x0+3.f,0.f),6.f) * (1.f/6.f));
                float h1 = rtf32(x1 * fminf(fmaxf(x1+3.f,0.f),6.f) * (1.f/6.f));
                int q = qb*QB + r;
                float* base = &g_HS[((size_t)b*SEQ_OUT + q)*OUT_PROJ + blk];
                base[s0p]     = h0;
                base[s0p + 2] = h1;
            }
        }
    }
}

// ============================================================
extern "C" void kernel_launch(void* const* d_in, const int* in_sizes, int n_in,
                              void* d_out, int out_size)
{
    const float* x      = (const float*)d_in[0];
    const float* kv_w   = (const float*)d_in[1];
    const float* kv_g   = (const float*)d_in[2];
    const float* kv_b   = (const float*)d_in[3];
    const float* kv_m   = (const float*)d_in[4];
    const float* kv_v   = (const float*)d_in[5];
    const float* q_w    = (const float*)d_in[6];
    const float* q_g    = (const float*)d_in[7];
    const float* q_b    = (const float*)d_in[8];
    const float* q_m    = (const float*)d_in[9];
    const float* q_v    = (const float*)d_in[10];
    const float* p_w    = (const float*)d_in[11];
    const float* p_g    = (const float*)d_in[12];
    const float* p_b    = (const float*)d_in[13];
    const float* p_m    = (const float*)d_in[14];
    const float* p_v    = (const float*)d_in[15];
    const float* biases = (const float*)d_in[16];
    const int*   bidx   = (const int*)d_in[17];
    float* out = (float*)d_out;

    cudaFuncSetAttribute(attn_tc, cudaFuncAttributeMaxDynamicSharedMemorySize, ATTN_BYTES);
    cudaFuncSetAttribute(gemm_tc<0>, cudaFuncAttributeMaxDynamicSharedMemorySize, GEMM_SMEM_BYTES);
    cudaFuncSetAttribute(gemm_tc<1>, cudaFuncAttributeMaxDynamicSharedMemorySize, GEMM_SMEM_BYTES);
    cudaFuncSetAttribute(gemm_tc<2>, cudaFuncAttributeMaxDynamicSharedMemorySize, GEMM_SMEM_BYTES);

    float *d_xr, *d_wkv, *d_wq, *d_wp;
    cudaGetSymbolAddress((void**)&d_xr,  g_Xr);
    cudaGetSymbolAddress((void**)&d_wkv, g_Wkv);
    cudaGetSymbolAddress((void**)&d_wq,  g_Wq);
    cudaGetSymbolAddress((void**)&d_wp,  g_Wp);

    round_perm_all<<<(N4_ALL + 255)/256, 256>>>(x, kv_w, q_w, p_w);
    bias_gather<<<(SEQ_OUT*SEQ + 255)/256, 256>>>(biases, bidx);

    // KV: [50176,512] x [2560,512]^T
    gemm_tc<0><<<dim3(50176/128, OUT_KV/128), 256, GEMM_SMEM_BYTES>>>(
        d_xr, d_wkv, kv_g, kv_b, kv_m, kv_v, nullptr, 50176, OUT_KV, C_IN);

    // Q: [12544,512] x [512,512]^T (strided row gather)
    gemm_tc<1><<<dim3(12544/128, 512/128), 256, GEMM_SMEM_BYTES>>>(
        d_xr, d_wq, q_g, q_b, q_m, q_v, nullptr, 12544, 512, C_IN);

    attn_tc<<<B_*NUM_HEADS*7, 256, ATTN_BYTES>>>();

    // Proj: [12544,2048] x [768,2048]^T -> d_out
    gemm_tc<2><<<dim3(12544/128, C_OUT/128), 256, GEMM_SMEM_BYTES>>>(
        nullptr, d_wp, p_g, p_b, p_m, p_v, out, 12544, C_OUT, OUT_PROJ);
}

// round 15
// speedup vs baseline: 1.0584x; 1.0584x over previous
#include <cuda_runtime.h>
#include <math.h>

#define B_        64
#define SEQ       784
#define SEQ_OUT   196
#define C_IN      512
#define KEY_DIM   32
#define NUM_HEADS 16
#define D_V       128
#define OUT_KV    2560
#define OUT_PROJ  2048
#define C_OUT     768
#define N_OFF     784
#define RES_OUT   14
#define SCALE_F   0.17677669529663687f
#define BN_EPS    1e-5f

// ---- scratch (static device globals; allocation-free) ----
__device__ float g_K   [(size_t)B_*NUM_HEADS*SEQ*KEY_DIM];   // d-permuted
__device__ float g_V   [(size_t)B_*NUM_HEADS*SEQ*D_V];
__device__ float g_Q   [(size_t)B_*NUM_HEADS*SEQ_OUT*KEY_DIM]; // d-permuted
__device__ float g_HS  [(size_t)B_*SEQ_OUT*OUT_PROJ];        // k-permuted
__device__ float g_Bias[(size_t)NUM_HEADS*SEQ_OUT*SEQ];
__device__ float g_Xr  [(size_t)B_*SEQ*C_IN];                // tf32, k-permuted
__device__ float g_Wkv [(size_t)OUT_KV*C_IN];                // tf32, k-permuted
__device__ float g_Wq  [(size_t)KEY_DIM*NUM_HEADS*C_IN];     // tf32, k-permuted
__device__ float g_Wp  [(size_t)C_OUT*OUT_PROJ];             // tf32, k-permuted

__device__ __forceinline__ unsigned f2tf32(float f) {
    unsigned r;
    asm("cvt.rna.tf32.f32 %0, %1;" : "=r"(r) : "f"(f));
    return r;
}
__device__ __forceinline__ float rtf32(float f) { return __uint_as_float(f2tf32(f)); }

__device__ __forceinline__ unsigned sm_u32(const void* p) {
    return (unsigned)__cvta_generic_to_shared(p);
}
#define CPA16(dst, src) asm volatile("cp.async.cg.shared.global [%0], [%1], 16;" :: "r"(dst), "l"(src))
#define CPCOMMIT()      asm volatile("cp.async.commit_group;")
#define CPWAIT(n)       asm volatile("cp.async.wait_group %0;" :: "n"(n))

__device__ __forceinline__ void mma_tf32(float* c, const unsigned* a, const unsigned* b) {
    asm volatile(
        "mma.sync.aligned.m16n8k8.row.col.f32.tf32.tf32.f32 "
        "{%0,%1,%2,%3}, {%4,%5,%6,%7}, {%8,%9}, {%0,%1,%2,%3};"
        : "+f"(c[0]), "+f"(c[1]), "+f"(c[2]), "+f"(c[3])
        : "r"(a[0]), "r"(a[1]), "r"(a[2]), "r"(a[3]), "r"(b[0]), "r"(b[1]));
}

// ============================================================
// Merged tf32 round + k-permutation for all four operands.
// slot(k) = 2*(k&3) + ((k&4)>>2) within each 8-block.
// ============================================================
#define N4_X  (B_*SEQ*C_IN/4)
#define N4_KV (OUT_KV*C_IN/4)
#define N4_Q  (KEY_DIM*NUM_HEADS*C_IN/4)
#define N4_P  (C_OUT*OUT_PROJ/4)
#define N4_ALL (N4_X + N4_KV + N4_Q + N4_P)

__global__ void round_perm_all(const float* __restrict__ x,
                               const float* __restrict__ kvw,
                               const float* __restrict__ qw,
                               const float* __restrict__ pw)
{
    int i = blockIdx.x * 256 + threadIdx.x;
    if (i >= N4_ALL) return;
    const float* src;
    float* dst;
    int j = i;
    if (j < N4_X)            { src = x;   dst = g_Xr;  }
    else if ((j -= N4_X) < N4_KV) { src = kvw; dst = g_Wkv; }
    else if ((j -= N4_KV) < N4_Q) { src = qw;  dst = g_Wq;  }
    else { j -= N4_Q;          src = pw;  dst = g_Wp;  }

    int o = j * 4, blk = o & ~7, s = o & 7;
    float4 v;
    float* pv = (float*)&v;
    #pragma unroll
    for (int e = 0; e < 4; e++) {
        int se = s + e;
        int k = (se & 1) ? 4 + (se >> 1) : (se >> 1);
        pv[e] = rtf32(src[blk + k]);
    }
    ((float4*)dst)[j] = v;
}

// ============================================================
// Bias pre-gather
// ============================================================
__global__ void bias_gather(const float* __restrict__ biases,
                            const int*   __restrict__ idxs)
{
    int i = blockIdx.x * 256 + threadIdx.x;
    if (i < SEQ_OUT * SEQ) {
        int idx = idxs[i];
        #pragma unroll
        for (int h = 0; h < NUM_HEADS; h++)
            g_Bias[(size_t)h * SEQ_OUT * SEQ + i] = biases[h * N_OFF + idx];
    }
}

// ============================================================
// TF32 GEMM (R10/R13): k-permuted operands, LDS.64 frag loads.
// ============================================================
#define GST  24
#define NSTG 4
#define GEMM_SMEM_BYTES (2*NSTG*128*GST*4)   // 98304

template<int MODE>
__global__ void __launch_bounds__(256, 2)
gemm_tc(const float* __restrict__ A, const float* __restrict__ W,
        const float* __restrict__ bng, const float* __restrict__ bnb,
        const float* __restrict__ bnm, const float* __restrict__ bnv,
        float* __restrict__ out, int M, int N, int K)
{
    extern __shared__ float smemf[];
    float* SA = smemf;
    float* SB = smemf + NSTG*128*GST;

    const int t    = threadIdx.x;
    const int warp = t >> 5, lane = t & 31;
    const int wm   = warp >> 2, wn = warp & 3;
    const int bm   = blockIdx.x * 128;
    const int bnn  = blockIdx.y * 128;
    const int lg   = lane >> 2, lc = lane & 3;

    const int r0 = t >> 2,        d0 = (t & 3) * 4;
    const int r1 = (t + 256) >> 2, d1 = ((t + 256) & 3) * 4;

    auto a_row = [&](int r) -> const float* {
        if (MODE == 1) {
            int row = bm + r;
            int b = row / SEQ_OUT, sq = row - b * SEQ_OUT;
            int rr = sq / RES_OUT, cc = sq - rr * RES_OUT;
            return A + ((size_t)b * SEQ + (2*rr*28 + 2*cc)) * C_IN;
        }
        if (MODE == 2) {
            return g_HS + (size_t)(bm + r) * K;
        }
        return A + (size_t)(bm + r) * K;
    };
    const float* aP0 = a_row(r0);
    const float* aP1 = a_row(r1);
    const float* bP0 = W + (size_t)(bnn + r0) * K;
    const float* bP1 = W + (size_t)(bnn + r1) * K;

    const unsigned sbase = sm_u32(smemf);
    const unsigned aA0 = sbase + (r0*GST + d0)*4;
    const unsigned aA1 = sbase + (r1*GST + d1)*4;
    const unsigned bA0 = sbase + (NSTG*128*GST + r0*GST + d0)*4;
    const unsigned bA1 = sbase + (NSTG*128*GST + r1*GST + d1)*4;

    auto issue = [&](int s, int k0) {
        unsigned so = s * 128*GST*4;
        CPA16(aA0 + so, aP0 + k0 + d0);
        CPA16(aA1 + so, aP1 + k0 + d1);
        CPA16(bA0 + so, bP0 + k0 + d0);
        CPA16(bA1 + so, bP1 + k0 + d1);
    };

    float acc[16][4];
    #pragma unroll
    for (int i = 0; i < 16; i++)
        #pragma unroll
        for (int j = 0; j < 4; j++) acc[i][j] = 0.f;

    const int nIter = K >> 4;
    #pragma unroll
    for (int s = 0; s < 3; s++) { issue(s, s << 4); CPCOMMIT(); }

    for (int it = 0; it < nIter; ++it) {
        CPWAIT(2);
        __syncthreads();
        const float* pA = SA + (it & 3) * 128*GST;
        const float* pB = SB + (it & 3) * 128*GST;

        #pragma unroll
        for (int g = 0; g < 2; g++) {
            const int ko = g*8 + 2*lc;
            unsigned af[4][4], bf[4][2];
            #pragma unroll
            for (int mt = 0; mt < 4; mt++) {
                int r = wm*64 + mt*16 + lg;
                uint2 p0 = *(const uint2*)&pA[r*GST + ko];
                uint2 p1 = *(const uint2*)&pA[(r+8)*GST + ko];
                af[mt][0] = p0.x;  af[mt][2] = p0.y;
                af[mt][1] = p1.x;  af[mt][3] = p1.y;
            }
            #pragma unroll
            for (int nt = 0; nt < 4; nt++) {
                int rn = wn*32 + nt*8 + lg;
                uint2 p = *(const uint2*)&pB[rn*GST + ko];
                bf[nt][0] = p.x;   bf[nt][1] = p.y;
            }
            #pragma unroll
            for (int mt = 0; mt < 4; mt++)
                #pragma unroll
                for (int nt = 0; nt < 4; nt++)
                    mma_tf32(acc[mt*4 + nt], af[mt], bf[nt]);
        }

        if (it + 3 < nIter) issue((it + 3) & 3, (it + 3) << 4);
        CPCOMMIT();
    }

    // ---- BN epilogue + scatter ----
    const int s0p = (lc < 2) ? 4*lc : 4*lc - 7;
    #pragma unroll
    for (int nt = 0; nt < 4; nt++) {
        int c0 = bnn + wn*32 + nt*8 + 2*lc;
        float sc0 = bng[c0]     * rsqrtf(bnv[c0]     + BN_EPS);
        float sh0 = bnb[c0]     - bnm[c0]     * sc0;
        float sc1 = bng[c0 + 1] * rsqrtf(bnv[c0 + 1] + BN_EPS);
        float sh1 = bnb[c0 + 1] - bnm[c0 + 1] * sc1;
        #pragma unroll
        for (int mt = 0; mt < 4; mt++) {
            #pragma unroll
            for (int half = 0; half < 2; half++) {
                int m = bm + wm*64 + mt*16 + lg + half*8;
                float y0 = acc[mt*4 + nt][half*2 + 0] * sc0 + sh0;
                float y1 = acc[mt*4 + nt][half*2 + 1] * sc1 + sh1;
                if (MODE == 0) {
                    int b = m / SEQ, s = m - b * SEQ;
                    int h = c0 / (KEY_DIM + D_V);
                    int c = c0 - h * (KEY_DIM + D_V);
                    if (c < KEY_DIM) {
                        float* base = &g_K[(((size_t)(b*NUM_HEADS+h))*SEQ + s)*KEY_DIM + (c & ~7)];
                        base[s0p]     = rtf32(y0);
                        base[s0p + 2] = rtf32(y1);
                    } else {
                        float* p = &g_V[(((size_t)(b*NUM_HEADS+h))*SEQ + s)*D_V + (c - KEY_DIM)];
                        p[0] = rtf32(y0); p[1] = rtf32(y1);
                    }
                } else if (MODE == 1) {
                    int b = m / SEQ_OUT, sq = m - b * SEQ_OUT;
                    int h = c0 / KEY_DIM, d = c0 - h * KEY_DIM;
                    float* base = &g_Q[(((size_t)(b*NUM_HEADS+h))*SEQ_OUT + sq)*KEY_DIM + (d & ~7)];
                    base[s0p]     = rtf32(y0);
                    base[s0p + 2] = rtf32(y1);
                } else {
                    float* p = &out[(size_t)m * C_OUT + c0];
                    p[0] = y0; p[1] = y1;
                }
            }
        }
    }
}

// ============================================================
// Flash-style tf32 attention — EXACT R13 (bias staged via cp.async
// into sB; ILP softmax; cross-chunk K/bias + V prefetch).
// ============================================================
#define QB  28
#define KC  112
#define NCH 7

#define QST 40
#define SST 120
#define W_SQ (32*QST)
#define W_SK (KC*QST)
#define W_SV 15232
#define W_SS (32*SST)
#define W_SB 3136
#define ATTN_WORDS (W_SQ + W_SK + W_SV + W_SS + W_SB + 96)
#define ATTN_BYTES (ATTN_WORDS * 4)

__global__ void __launch_bounds__(256, 2)
attn_tc()
{
    extern __shared__ unsigned smw[];
    unsigned* sQ = smw;
    unsigned* sK = sQ + W_SQ;
    unsigned* sV = sK + W_SK;
    float*    sS = (float*)(sV + W_SV);
    float*    sB = sS + W_SS;
    float*    sM = sB + W_SB;
    float*    sL = sM + 32;
    float*    sF = sL + 32;

    const int t    = threadIdx.x;
    const int warp = t >> 5, lane = t & 31;
    const int cta  = blockIdx.x;
    const int qb   = cta % 7;
    const int h    = (cta / 7) % NUM_HEADS;
    const int b    = cta / (7 * NUM_HEADS);

    const float* Kp = g_K + ((size_t)(b*NUM_HEADS+h))*SEQ*KEY_DIM;
    const float* Vp = g_V + ((size_t)(b*NUM_HEADS+h))*SEQ*D_V;
    const float* Qp = g_Q + (((size_t)(b*NUM_HEADS+h))*SEQ_OUT + qb*QB)*KEY_DIM;
    const float* Bp = g_Bias + ((size_t)h*SEQ_OUT + qb*QB)*SEQ;

    const unsigned sKb = sm_u32(sK);
    const unsigned sVb = sm_u32(sV);
    const unsigned sBb = sm_u32(sB);

    auto stage_kbias = [&](int kc) {
        for (int i = t*4; i < KC*KEY_DIM; i += 1024) {
            int r = i >> 5, d = i & 31;
            CPA16(sKb + (r*QST + d)*4, &Kp[(size_t)kc*KEY_DIM + i]);
        }
        for (int i = t*4; i < QB*KC; i += 1024) {
            int r = i / KC, c = i - r*KC;
            CPA16(sBb + (r*KC + c)*4, &Bp[(size_t)r*SEQ + kc + c]);
        }
        CPCOMMIT();
    };
    auto stage_v = [&](int kc) {
        for (int i = t*4; i < KC*D_V; i += 1024) {
            int r = i >> 7, d = i & 127;
            CPA16(sVb + (r*136 + d)*4, &Vp[(size_t)kc*D_V + i]);
        }
        CPCOMMIT();
    };

    for (int i = t; i < 32*32; i += 256) {
        int r = i >> 5, d = i & 31;
        float v = (r < QB) ? Qp[r*KEY_DIM + d] : 0.f;
        sQ[r*QST + d] = __float_as_uint(v);
    }
    if (t < 32) { sM[t] = -1e30f; sL[t] = 0.f; sF[t] = 1.f; }

    // prologue: chunk 0 staging
    stage_kbias(0);   // A0
    stage_v(0);       // B0

    float acc[2][2][4];
    #pragma unroll
    for (int mt = 0; mt < 2; mt++)
        #pragma unroll
        for (int nt = 0; nt < 2; nt++)
            #pragma unroll
            for (int e = 0; e < 4; e++) acc[mt][nt][e] = 0.f;

    const int lg = lane >> 2;
    const int lc = lane & 3;
    const int s0p = (lc < 2) ? 4*lc : 4*lc - 7;

    for (int ch = 0; ch < NCH; ch++) {
        // A_ch (K+bias) done; B_ch (V) may still be in flight
        CPWAIT(1);
        __syncthreads();

        // ---- QK^T (uint2 fragment loads from permuted sQ/sK) ----
        {
            int nt0 = (warp < 6) ? warp*2 : 6 + warp;
            int ntc = (warp < 6) ? 2 : 1;
            for (int nti = 0; nti < ntc; nti++) {
                int ntile = nt0 + nti;
                float c[2][4] = {};
                #pragma unroll
                for (int ks = 0; ks < 4; ks++) {
                    const int ko = ks*8 + 2*lc;
                    uint2 kk2 = *(const uint2*)&sK[(ntile*8 + lg)*QST + ko];
                    unsigned bb[2] = { kk2.x, kk2.y };
                    #pragma unroll
                    for (int mt = 0; mt < 2; mt++) {
                        int r0 = mt*16 + lg;
                        uint2 q0 = *(const uint2*)&sQ[r0*QST + ko];
                        uint2 q1 = *(const uint2*)&sQ[(r0+8)*QST + ko];
                        unsigned a[4] = { q0.x, q1.x, q0.y, q1.y };
                        mma_tf32(c[mt], a, bb);
                    }
                }
                #pragma unroll
                for (int mt = 0; mt < 2; mt++) {
                    int r0 = mt*16 + lg;
                    int col = ntile*8 + 2*lc;
                    int ps  = ntile*8 + s0p;
                    float b00 = (r0   < QB) ? sB[r0*KC + col]       : 0.f;
                    float b01 = (r0   < QB) ? sB[r0*KC + col + 1]   : 0.f;
                    float b10 = (r0+8 < QB) ? sB[(r0+8)*KC + col]   : 0.f;
                    float b11 = (r0+8 < QB) ? sB[(r0+8)*KC + col+1] : 0.f;
                    sS[r0*SST + ps]           = c[mt][0]*SCALE_F + b00;
                    sS[r0*SST + ps + 2]       = c[mt][1]*SCALE_F + b01;
                    sS[(r0+8)*SST + ps]       = c[mt][2]*SCALE_F + b10;
                    sS[(r0+8)*SST + ps + 2]   = c[mt][3]*SCALE_F + b11;
                }
            }
        }
        __syncthreads();   // all warps done reading sK / sB

        // prefetch next chunk's K + bias into the (now dead) buffers
        if (ch + 1 < NCH) stage_kbias((ch + 1) * KC);   // A_{ch+1}

        // ---- online softmax: warps 0-6 x 4 rows, interleaved chains ----
        if (warp < 7) {
            float4 v[4];
            float  mx[4], sum[4];
            #pragma unroll
            for (int i = 0; i < 4; i++) {
                int q = warp*4 + i;
                if (lane < 28) v[i] = *(const float4*)&sS[q*SST + lane*4];
                else v[i] = make_float4(-1e30f, -1e30f, -1e30f, -1e30f);
                mx[i] = fmaxf(fmaxf(v[i].x, v[i].y), fmaxf(v[i].z, v[i].w));
            }
            #pragma unroll
            for (int o = 16; o; o >>= 1) {
                #pragma unroll
                for (int i = 0; i < 4; i++)
                    mx[i] = fmaxf(mx[i], __shfl_xor_sync(~0u, mx[i], o));
            }
            float m_new[4], fac[4];
            #pragma unroll
            for (int i = 0; i < 4; i++) {
                int q = warp*4 + i;
                float m_old = sM[q];
                m_new[i] = fmaxf(m_old, mx[i]);
                fac[i]   = __expf(m_old - m_new[i]);
                float e0 = __expf(v[i].x - m_new[i]);
                float e1 = __expf(v[i].y - m_new[i]);
                float e2 = __expf(v[i].z - m_new[i]);
                float e3 = __expf(v[i].w - m_new[i]);
                v[i] = make_float4(e0, e1, e2, e3);
                sum[i] = (lane < 28) ? (e0 + e1 + e2 + e3) : 0.f;
            }
            #pragma unroll
            for (int o = 16; o; o >>= 1) {
                #pragma unroll
                for (int i = 0; i < 4; i++)
                    sum[i] += __shfl_xor_sync(~0u, sum[i], o);
            }
            #pragma unroll
            for (int i = 0; i < 4; i++) {
                int q = warp*4 + i;
                if (lane < 28)
                    *(float4*)&sS[q*SST + lane*4] = v[i];   // un-rounded P
                if (lane == 0) {
                    sM[q] = m_new[i];
                    sL[q] = sL[q]*fac[i] + sum[i];
                    sF[q] = fac[i];
                }
            }
        }

        // B_ch (V) done; A_{ch+1} may remain in flight
        if (ch + 1 < NCH) { CPWAIT(1); } else { CPWAIT(0); }
        __syncthreads();

        // ---- rescale accumulators ----
        {
            float f00 = sF[lg],      f01 = sF[lg + 8];
            float f10 = sF[lg + 16], f11 = sF[lg + 24];
            #pragma unroll
            for (int nt = 0; nt < 2; nt++) {
                acc[0][nt][0] *= f00; acc[0][nt][1] *= f00;
                acc[0][nt][2] *= f01; acc[0][nt][3] *= f01;
                acc[1][nt][0] *= f10; acc[1][nt][1] *= f10;
                acc[1][nt][2] *= f11; acc[1][nt][3] *= f11;
            }
        }

        // ---- PV accumulate ----
        #pragma unroll
        for (int ks = 0; ks < 14; ks++) {
            const int ko = ks*8 + 2*lc;
            unsigned a[2][4];
            #pragma unroll
            for (int mt = 0; mt < 2; mt++) {
                int r0 = mt*16 + lg;
                uint2 p0 = *(const uint2*)&sS[r0*SST + ko];
                uint2 p1 = *(const uint2*)&sS[(r0+8)*SST + ko];
                a[mt][0] = p0.x; a[mt][2] = p0.y;
                a[mt][1] = p1.x; a[mt][3] = p1.y;
            }
            #pragma unroll
            for (int nt = 0; nt < 2; nt++) {
                int n = warp*16 + nt*8 + lg;
                unsigned bb[2];
                bb[0] = sV[(ks*8 + lc)*136 + n];
                bb[1] = sV[(ks*8 + lc + 4)*136 + n];
                mma_tf32(acc[0][nt], a[0], bb);
                mma_tf32(acc[1][nt], a[1], bb);
            }
        }
        __syncthreads();   // all warps done reading sV (and sS)

        // prefetch next chunk's V into the dead sV buffer
        if (ch + 1 < NCH) stage_v((ch + 1) * KC);       // B_{ch+1}
    }

    // ---- epilogue: /l, hardswish, tf32-round, k-permuted HS store ----
    #pragma unroll
    for (int mt = 0; mt < 2; mt++) {
        int rA = mt*16 + lg, rB = rA + 8;
        float invA = 1.f / sL[rA];
        float invB = 1.f / sL[rB];
        #pragma unroll
        for (int nt = 0; nt < 2; nt++) {
            int blk = h*D_V + warp*16 + nt*8;
            #pragma unroll
            for (int half = 0; half < 2; half++) {
                int r = half ? rB : rA;
                if (r >= QB) continue;
                float inv = half ? invB : invA;
                float x0 = acc[mt][nt][half*2 + 0]*inv;
                float x1 = acc[mt][nt][half*2 + 1]*inv;
                float h0 = rtf32(x0 * fminf(fmaxf(x0+3.f,0.f),6.f) * (1.f/6.f));
                float h1 = rtf32(x1 * fminf(fmaxf(x1+3.f,0.f),6.f) * (1.f/6.f));
                int q = qb*QB + r;
                float* base = &g_HS[((size_t)b*SEQ_OUT + q)*OUT_PROJ + blk];
                base[s0p]     = h0;
                base[s0p + 2] = h1;
            }
        }
    }
}

// ============================================================
extern "C" void kernel_launch(void* const* d_in, const int* in_sizes, int n_in,
                              void* d_out, int out_size)
{
    const float* x      = (const float*)d_in[0];
    const float* kv_w   = (const float*)d_in[1];
    const float* kv_g   = (const float*)d_in[2];
    const float* kv_b   = (const float*)d_in[3];
    const float* kv_m   = (const float*)d_in[4];
    const float* kv_v   = (const float*)d_in[5];
    const float* q_w    = (const float*)d_in[6];
    const float* q_g    = (const float*)d_in[7];
    const float* q_b    = (const float*)d_in[8];
    const float* q_m    = (const float*)d_in[9];
    const float* q_v    = (const float*)d_in[10];
    const float* p_w    = (const float*)d_in[11];
    const float* p_g    = (const float*)d_in[12];
    const float* p_b    = (const float*)d_in[13];
    const float* p_m    = (const float*)d_in[14];
    const float* p_v    = (const float*)d_in[15];
    const float* biases = (const float*)d_in[16];
    const int*   bidx   = (const int*)d_in[17];
    float* out = (float*)d_out;

    cudaFuncSetAttribute(attn_tc, cudaFuncAttributeMaxDynamicSharedMemorySize, ATTN_BYTES);
    cudaFuncSetAttribute(gemm_tc<0>, cudaFuncAttributeMaxDynamicSharedMemorySize, GEMM_SMEM_BYTES);
    cudaFuncSetAttribute(gemm_tc<1>, cudaFuncAttributeMaxDynamicSharedMemorySize, GEMM_SMEM_BYTES);
    cudaFuncSetAttribute(gemm_tc<2>, cudaFuncAttributeMaxDynamicSharedMemorySize, GEMM_SMEM_BYTES);

    float *d_xr, *d_wkv, *d_wq, *d_wp;
    cudaGetSymbolAddress((void**)&d_xr,  g_Xr);
    cudaGetSymbolAddress((void**)&d_wkv, g_Wkv);
    cudaGetSymbolAddress((void**)&d_wq,  g_Wq);
    cudaGetSymbolAddress((void**)&d_wp,  g_Wp);

    round_perm_all<<<(N4_ALL + 255)/256, 256>>>(x, kv_w, q_w, p_w);
    bias_gather<<<(SEQ_OUT*SEQ + 255)/256, 256>>>(biases, bidx);

    // KV: [50176,512] x [2560,512]^T
    gemm_tc<0><<<dim3(50176/128, OUT_KV/128), 256, GEMM_SMEM_BYTES>>>(
        d_xr, d_wkv, kv_g, kv_b, kv_m, kv_v, nullptr, 50176, OUT_KV, C_IN);

    // Q: [12544,512] x [512,512]^T (strided row gather)
    gemm_tc<1><<<dim3(12544/128, 512/128), 256, GEMM_SMEM_BYTES>>>(
        d_xr, d_wq, q_g, q_b, q_m, q_v, nullptr, 12544, 512, C_IN);

    attn_tc<<<B_*NUM_HEADS*7, 256, ATTN_BYTES>>>();

    // Proj: [12544,2048] x [768,2048]^T -> d_out
    gemm_tc<2><<<dim3(12544/128, C_OUT/128), 256, GEMM_SMEM_BYTES>>>(
        nullptr, d_wp, p_g, p_b, p_m, p_v, out, 12544, C_OUT, OUT_PROJ);
}